// round 4
// baseline (speedup 1.0000x reference)
#include <cuda_runtime.h>
#include <cuda_bf16.h>
#include <math.h>

// Problem constants
#define BATCH 4
#define SEQ   2048
#define EMB   1024
#define HEADS 16
#define DK    64
#define MROWS (BATCH*SEQ)   // 8192

// ---------------------------------------------------------------------------
// Scratch (no allocations allowed): Q, K, V projections and attention output,
// all in [B*S, E] row-major layout (head h occupies columns h*64 .. h*64+63).
// ---------------------------------------------------------------------------
__device__ float g_Qp[MROWS * EMB];
__device__ float g_Kp[MROWS * EMB];
__device__ float g_Vp[MROWS * EMB];
__device__ float g_Ap[MROWS * EMB];

// ---------------------------------------------------------------------------
// SGEMM: C[M,N] = A[M,K] * B[K,N], fp32, N=K=1024 fixed, M=8192.
// 128x128 block tile, BK=16, 256 threads, 8x8 per-thread micro-tile.
// ---------------------------------------------------------------------------
#define BM 128
#define BN 128
#define BK 16
#define TM 8
#define TN 8

__global__ void __launch_bounds__(256, 2) sgemm_kernel(
    const float* __restrict__ A, const float* __restrict__ B,
    float* __restrict__ C)
{
    const int N = EMB, K = EMB;
    __shared__ float As[BK][BM];  // transposed A tile
    __shared__ float Bs[BK][BN];

    const int tid = threadIdx.x;
    const int bm = blockIdx.y, bn = blockIdx.x;
    const int tRow = tid >> 4;   // 0..15
    const int tCol = tid & 15;   // 0..15

    // A tile load mapping: 128 rows x 4 quads-of-K, 2 rows per thread
    const int aRow = tid >> 2;           // 0..63
    const int aK4  = (tid & 3) << 2;     // 0,4,8,12
    // B tile load mapping: 16 rows x 32 quads, 2 rows per thread
    const int bRow = tid >> 5;           // 0..7
    const int bC4  = (tid & 31) << 2;    // 0..124

    const float* Ab = A + (long long)(bm * BM) * K;
    const float* Bb = B + bn * BN;

    float acc[TM][TN];
    #pragma unroll
    for (int i = 0; i < TM; i++)
        #pragma unroll
        for (int j = 0; j < TN; j++) acc[i][j] = 0.f;

    for (int k0 = 0; k0 < K; k0 += BK) {
        // Load A tile (transposed into As)
        #pragma unroll
        for (int r = 0; r < 2; r++) {
            const int row = aRow + r * 64;
            float4 v = *(const float4*)(Ab + (long long)row * K + k0 + aK4);
            As[aK4 + 0][row] = v.x;
            As[aK4 + 1][row] = v.y;
            As[aK4 + 2][row] = v.z;
            As[aK4 + 3][row] = v.w;
        }
        // Load B tile
        #pragma unroll
        for (int r = 0; r < 2; r++) {
            const int row = bRow + r * 8;
            float4 v = *(const float4*)(Bb + (long long)(k0 + row) * N + bC4);
            *(float4*)&Bs[row][bC4] = v;
        }
        __syncthreads();

        #pragma unroll
        for (int k = 0; k < BK; k++) {
            float a_frag[TM], b_frag[TN];
            #pragma unroll
            for (int i = 0; i < TM; i++) a_frag[i] = As[k][tRow * TM + i];
            #pragma unroll
            for (int j = 0; j < TN; j++) b_frag[j] = Bs[k][tCol * TN + j];
            #pragma unroll
            for (int i = 0; i < TM; i++)
                #pragma unroll
                for (int j = 0; j < TN; j++)
                    acc[i][j] += a_frag[i] * b_frag[j];
        }
        __syncthreads();
    }

    float* Cb = C + (long long)(bm * BM + tRow * TM) * N + bn * BN + tCol * TN;
    #pragma unroll
    for (int i = 0; i < TM; i++) {
        *(float4*)(Cb + (long long)i * N + 0) =
            make_float4(acc[i][0], acc[i][1], acc[i][2], acc[i][3]);
        *(float4*)(Cb + (long long)i * N + 4) =
            make_float4(acc[i][4], acc[i][5], acc[i][6], acc[i][7]);
    }
}

// ---------------------------------------------------------------------------
// Causal flash attention, fp32. One CTA = (query block of 64 rows, head, batch).
// BR=64, BC=32, dk=64. 256 threads = 16(ty, rows) x 16(tx, cols).
// Score micro-tile: 4 rows x 2 cols per thread. Output: 4 rows x 4 dcols.
// Online softmax with row reductions over the 16 tx lanes via shfl butterfly.
// ---------------------------------------------------------------------------
#define FBR 64
#define FBC 32

__global__ void __launch_bounds__(256) flash_attn_kernel(
    const float* __restrict__ Qg, const float* __restrict__ Kg,
    const float* __restrict__ Vg, float* __restrict__ Og)
{
    __shared__ float Qs[FBR][DK + 4];   // pad 4: float4-aligned rows, spread banks
    __shared__ float Ks[FBC][DK + 1];   // pad 1: scalar access pattern
    __shared__ float Vs[FBC][DK + 4];
    __shared__ float Ps[FBR][FBC + 1];

    const int qb = blockIdx.x;   // 0..31
    const int h  = blockIdx.y;   // 0..15
    const int b  = blockIdx.z;   // 0..3
    const int tid = threadIdx.x;
    const int ty = tid >> 4;     // 0..15 (row group)
    const int tx = tid & 15;     // 0..15 (col group)

    const long long qrowbase = ((long long)(b * SEQ + qb * FBR)) * EMB + h * DK;
    const long long khbase   = ((long long)b * SEQ) * EMB + h * DK;

    // Load Q tile: 64 rows x 64 cols
    for (int i = tid; i < FBR * (DK / 4); i += 256) {
        const int r = i >> 4;
        const int q4 = (i & 15) << 2;
        float4 v = *(const float4*)(Qg + qrowbase + (long long)r * EMB + q4);
        *(float4*)&Qs[r][q4] = v;
    }

    float m_i[4], l_i[4], acc[4][4];
    #pragma unroll
    for (int i = 0; i < 4; i++) {
        m_i[i] = -INFINITY; l_i[i] = 0.f;
        #pragma unroll
        for (int j = 0; j < 4; j++) acc[i][j] = 0.f;
    }

    __syncthreads();

    const int kbmax = 2 * qb + 1;  // causal bound: key block start <= last query row
    for (int kb = 0; kb <= kbmax; kb++) {
        // Load K/V tiles: 32 rows x 64 cols each
        for (int i = tid; i < FBC * (DK / 4); i += 256) {
            const int r = i >> 4;
            const int q4 = (i & 15) << 2;
            const long long g = khbase + (long long)(kb * FBC + r) * EMB + q4;
            float4 k4 = *(const float4*)(Kg + g);
            Ks[r][q4 + 0] = k4.x; Ks[r][q4 + 1] = k4.y;
            Ks[r][q4 + 2] = k4.z; Ks[r][q4 + 3] = k4.w;
            float4 v4 = *(const float4*)(Vg + g);
            *(float4*)&Vs[r][q4] = v4;
        }
        __syncthreads();

        // S = Q K^T  (4 rows x 2 cols per thread)
        float s0[4], s1[4];
        #pragma unroll
        for (int i = 0; i < 4; i++) { s0[i] = 0.f; s1[i] = 0.f; }
        #pragma unroll 8
        for (int d = 0; d < DK; d++) {
            const float kv0 = Ks[tx * 2 + 0][d];
            const float kv1 = Ks[tx * 2 + 1][d];
            #pragma unroll
            for (int i = 0; i < 4; i++) {
                const float qv = Qs[ty * 4 + i][d];
                s0[i] += qv * kv0;
                s1[i] += qv * kv1;
            }
        }

        // Scale + causal mask + online softmax update
        #pragma unroll
        for (int i = 0; i < 4; i++) {
            const int qrow = qb * FBR + ty * 4 + i;
            const int kc0 = kb * FBC + tx * 2;
            const float v0 = (kc0     <= qrow) ? s0[i] * 0.125f : -INFINITY;
            const float v1 = (kc0 + 1 <= qrow) ? s1[i] * 0.125f : -INFINITY;

            float rmax = fmaxf(v0, v1);
            #pragma unroll
            for (int w = 1; w < 16; w <<= 1)
                rmax = fmaxf(rmax, __shfl_xor_sync(0xffffffffu, rmax, w));

            const float mn = fmaxf(m_i[i], rmax);          // finite after kb=0
            const float alpha = __expf(m_i[i] - mn);       // 0 on first block
            const float p0 = __expf(v0 - mn);
            const float p1 = __expf(v1 - mn);

            float rs = p0 + p1;
            #pragma unroll
            for (int w = 1; w < 16; w <<= 1)
                rs += __shfl_xor_sync(0xffffffffu, rs, w);

            l_i[i] = l_i[i] * alpha + rs;
            m_i[i] = mn;
            #pragma unroll
            for (int j = 0; j < 4; j++) acc[i][j] *= alpha;

            Ps[ty * 4 + i][tx * 2 + 0] = p0;
            Ps[ty * 4 + i][tx * 2 + 1] = p1;
        }
        __syncthreads();

        // O += P V  (4 rows x 4 dcols per thread; dcols = tx*4..tx*4+3)
        #pragma unroll 4
        for (int c = 0; c < FBC; c++) {
            const float4 v4 = *(const float4*)&Vs[c][tx * 4];
            #pragma unroll
            for (int i = 0; i < 4; i++) {
                const float p = Ps[ty * 4 + i][c];
                acc[i][0] += p * v4.x;
                acc[i][1] += p * v4.y;
                acc[i][2] += p * v4.z;
                acc[i][3] += p * v4.w;
            }
        }
        __syncthreads();
    }

    // Normalize and store: rows ty*4+i, dcols tx*4..+3
    #pragma unroll
    for (int i = 0; i < 4; i++) {
        const float inv = 1.f / l_i[i];
        float4 o = make_float4(acc[i][0] * inv, acc[i][1] * inv,
                               acc[i][2] * inv, acc[i][3] * inv);
        *(float4*)(Og + qrowbase + (long long)(ty * 4 + i) * EMB + tx * 4) = o;
    }
}

// ---------------------------------------------------------------------------
// Launch
// ---------------------------------------------------------------------------
extern "C" void kernel_launch(void* const* d_in, const int* in_sizes, int n_in,
                              void* d_out, int out_size)
{
    const float* x  = (const float*)d_in[0];
    const float* WQ = (const float*)d_in[1];
    const float* WK = (const float*)d_in[2];
    const float* WV = (const float*)d_in[3];
    const float* WO = (const float*)d_in[4];
    float* out = (float*)d_out;

    void *pQ, *pK, *pV, *pA;
    cudaGetSymbolAddress(&pQ, g_Qp);
    cudaGetSymbolAddress(&pK, g_Kp);
    cudaGetSymbolAddress(&pV, g_Vp);
    cudaGetSymbolAddress(&pA, g_Ap);

    dim3 gGrid(EMB / BN, MROWS / BM);   // (8, 64)
    sgemm_kernel<<<gGrid, 256>>>(x, WQ, (float*)pQ);
    sgemm_kernel<<<gGrid, 256>>>(x, WK, (float*)pK);
    sgemm_kernel<<<gGrid, 256>>>(x, WV, (float*)pV);

    dim3 fGrid(SEQ / FBR, HEADS, BATCH); // (32, 16, 4)
    flash_attn_kernel<<<fGrid, 256>>>((const float*)pQ, (const float*)pK,
                                      (const float*)pV, (float*)pA);

    sgemm_kernel<<<gGrid, 256>>>((const float*)pA, WO, out);
}

// round 9
// speedup vs baseline: 1.6309x; 1.6309x over previous
#include <cuda_runtime.h>
#include <cuda_bf16.h>
#include <math.h>
#include <stdint.h>

// Problem constants
#define BATCH 4
#define SEQ   2048
#define EMB   1024
#define HEADS 16
#define DK    64
#define MROWS (BATCH*SEQ)   // 8192

// ---------------------------------------------------------------------------
// Scratch (static device arrays; no allocations allowed)
// ---------------------------------------------------------------------------
__device__ float g_Qp[MROWS * EMB];
__device__ float g_Kp[MROWS * EMB];
__device__ float g_Vp[MROWS * EMB];
__device__ float g_Ap[MROWS * EMB];

__device__ __nv_bfloat16 g_xh[MROWS * EMB];   // x split hi
__device__ __nv_bfloat16 g_xl[MROWS * EMB];   // x split lo
__device__ __nv_bfloat16 g_ah[MROWS * EMB];   // attn out split hi
__device__ __nv_bfloat16 g_al[MROWS * EMB];   // attn out split lo
__device__ __nv_bfloat16 g_wh[4][EMB * EMB];  // W^T split hi  [n][k]
__device__ __nv_bfloat16 g_wl[4][EMB * EMB];  // W^T split lo  [n][k]

// ---------------------------------------------------------------------------
// PTX helpers (sm_80-era only: cp.async, ldmatrix, mma.sync — all legal on
// plain sm_103 PTX target; NO tcgen05 / arch-feature instructions)
// ---------------------------------------------------------------------------
__device__ __forceinline__ uint32_t s2u(const void* p) {
    uint32_t a;
    asm("{ .reg .u64 t; cvta.to.shared.u64 t, %1; cvt.u32.u64 %0, t; }"
        : "=r"(a) : "l"(p));
    return a;
}

__device__ __forceinline__ void cpasync16(uint32_t dst, const void* src) {
    asm volatile("cp.async.cg.shared.global [%0], [%1], 16;"
                 :: "r"(dst), "l"(src));
}
#define CP_COMMIT() asm volatile("cp.async.commit_group;" ::: "memory")

__device__ __forceinline__ void ldx4(uint32_t* r, uint32_t addr) {
    asm volatile("ldmatrix.sync.aligned.m8n8.x4.shared.b16 {%0,%1,%2,%3}, [%4];"
                 : "=r"(r[0]), "=r"(r[1]), "=r"(r[2]), "=r"(r[3])
                 : "r"(addr));
}

__device__ __forceinline__ void mma_bf16(float* d, const uint32_t* a,
                                         uint32_t b0, uint32_t b1) {
    asm volatile("mma.sync.aligned.m16n8k16.row.col.f32.bf16.bf16.f32 "
                 "{%0,%1,%2,%3}, {%4,%5,%6,%7}, {%8,%9}, {%0,%1,%2,%3};"
                 : "+f"(d[0]), "+f"(d[1]), "+f"(d[2]), "+f"(d[3])
                 : "r"(a[0]), "r"(a[1]), "r"(a[2]), "r"(a[3]),
                   "r"(b0), "r"(b1));
}

// ---------------------------------------------------------------------------
// Split kernel: fp32 -> (bf16 hi, bf16 lo residual)
// ---------------------------------------------------------------------------
__global__ void split_kernel(const float* __restrict__ in,
                             __nv_bfloat16* __restrict__ hi,
                             __nv_bfloat16* __restrict__ lo, int n)
{
    int i = (blockIdx.x * blockDim.x + threadIdx.x) * 4;
    if (i >= n) return;
    float4 v = *(const float4*)(in + i);
    __nv_bfloat16 h0 = __float2bfloat16(v.x);
    __nv_bfloat16 h1 = __float2bfloat16(v.y);
    __nv_bfloat16 h2 = __float2bfloat16(v.z);
    __nv_bfloat16 h3 = __float2bfloat16(v.w);
    __nv_bfloat16 l0 = __float2bfloat16(v.x - __bfloat162float(h0));
    __nv_bfloat16 l1 = __float2bfloat16(v.y - __bfloat162float(h1));
    __nv_bfloat16 l2 = __float2bfloat16(v.z - __bfloat162float(h2));
    __nv_bfloat16 l3 = __float2bfloat16(v.w - __bfloat162float(h3));
    *(__nv_bfloat162*)(hi + i)     = __nv_bfloat162(h0, h1);
    *(__nv_bfloat162*)(hi + i + 2) = __nv_bfloat162(h2, h3);
    *(__nv_bfloat162*)(lo + i)     = __nv_bfloat162(l0, l1);
    *(__nv_bfloat162*)(lo + i + 2) = __nv_bfloat162(l2, l3);
}

// ---------------------------------------------------------------------------
// Weight transpose + split: Wt[n][k] = split(W[k][n]), 32x32 smem tiles
// ---------------------------------------------------------------------------
__global__ void wsplit_kernel(const float* __restrict__ W,
                              __nv_bfloat16* __restrict__ ht,
                              __nv_bfloat16* __restrict__ lt)
{
    __shared__ float t[32][33];
    const int tx = threadIdx.x, ty = threadIdx.y;      // 32 x 8
    const int n0 = blockIdx.x * 32, k0 = blockIdx.y * 32;
    #pragma unroll
    for (int j = 0; j < 4; j++)
        t[ty + 8 * j][tx] = W[(size_t)(k0 + ty + 8 * j) * EMB + n0 + tx];
    __syncthreads();
    #pragma unroll
    for (int j = 0; j < 4; j++) {
        float v = t[tx][ty + 8 * j];
        __nv_bfloat16 h = __float2bfloat16(v);
        __nv_bfloat16 l = __float2bfloat16(v - __bfloat162float(h));
        size_t o = (size_t)(n0 + ty + 8 * j) * EMB + k0 + tx;
        ht[o] = h;
        lt[o] = l;
    }
}

// ---------------------------------------------------------------------------
// HMMA split-bf16 GEMM: C[8192,1024] = A * W via Ah*Bh + Ah*Bl + Al*Bh.
// A hi/lo: [M,K] bf16 K-major. B hi/lo: [N,K] bf16 K-major (W pre-transposed).
// CTA tile 128x128, BK=32, 2-stage cp.async pipeline, 256 threads (8 warps in
// 4x2; each warp owns 32x64 = 2x8 m16n8k16 accum tiles). Occupancy 2.
// SMEM tile rows padded to 80B -> ldmatrix bank-conflict-free (r*5 mod 8 perm).
// ---------------------------------------------------------------------------
#define GBK       32
#define NCHUNK    (EMB / GBK)          // 32
#define TILE_B    (128 * 80)           // 10240 B per operand tile
#define STAGE_B   (4 * TILE_B)         // Ah, Al, Bh, Bl = 40960 B
#define GEMM_SMEM (2 * STAGE_B)        // 81920 B

__device__ __forceinline__ void load_chunk(uint32_t st,
    const __nv_bfloat16* Ah, const __nv_bfloat16* Al,
    const __nv_bfloat16* Bh, const __nv_bfloat16* Bl,
    int k0, int tid)
{
    const __nv_bfloat16* srcs[4] = { Ah, Al, Bh, Bl };
    #pragma unroll
    for (int t = 0; t < 4; t++) {
        const char* base = (const char*)srcs[t] + (size_t)k0 * 2;
        #pragma unroll
        for (int j = 0; j < 2; j++) {
            int idx = tid + j * 256;       // 0..511
            int row = idx >> 2;            // 0..127
            int c16 = (idx & 3) * 16;      // 0,16,32,48
            cpasync16(st + t * TILE_B + row * 80 + c16,
                      base + (size_t)row * (EMB * 2) + c16);
        }
    }
}

__global__ void __launch_bounds__(256, 2) gemm_hmma_kernel(
    const __nv_bfloat16* __restrict__ Ah, const __nv_bfloat16* __restrict__ Al,
    const __nv_bfloat16* __restrict__ Bh, const __nv_bfloat16* __restrict__ Bl,
    float* __restrict__ C)
{
    extern __shared__ char smem[];
    const uint32_t sb = s2u(smem);
    const int tid = threadIdx.x;
    const int wid = tid >> 5, l = tid & 31;
    const int wm = wid & 3;        // warp row  (0..3)  -> rows wm*32
    const int wn = wid >> 2;       // warp col  (0..1)  -> cols wn*64
    const int bn = blockIdx.x, bm = blockIdx.y;

    const __nv_bfloat16* Ahb = Ah + (size_t)bm * 128 * EMB;
    const __nv_bfloat16* Alb = Al + (size_t)bm * 128 * EMB;
    const __nv_bfloat16* Bhb = Bh + (size_t)bn * 128 * EMB;
    const __nv_bfloat16* Blb = Bl + (size_t)bn * 128 * EMB;

    // Per-lane ldmatrix byte offsets within a tile (row stride 80B)
    // A (m16k16 .x4): row = warp_m + (l&15), +16B for lanes 16-31
    int aoffm[2];
    #pragma unroll
    for (int mi = 0; mi < 2; mi++)
        aoffm[mi] = (wm * 32 + mi * 16 + (l & 15)) * 80 + ((l >> 4) & 1) * 16;
    // B (two n8 tiles per .x4): rows = n, mats: n0-7@k0, n0-7@k8, n8-15@k0, n8-15@k8
    int boffp[4];
    #pragma unroll
    for (int p = 0; p < 4; p++)
        boffp[p] = (wn * 64 + p * 16 + (l & 7) + ((l >> 4) << 3)) * 80
                 + ((l >> 3) & 1) * 16;

    float acc[2][8][4];
    #pragma unroll
    for (int mi = 0; mi < 2; mi++)
        #pragma unroll
        for (int ni = 0; ni < 8; ni++)
            #pragma unroll
            for (int r = 0; r < 4; r++) acc[mi][ni][r] = 0.f;

    // Prologue: chunks 0,1 -> stages 0,1
    load_chunk(sb + 0 * STAGE_B, Ahb, Alb, Bhb, Blb, 0 * GBK, tid);
    CP_COMMIT();
    load_chunk(sb + 1 * STAGE_B, Ahb, Alb, Bhb, Blb, 1 * GBK, tid);
    CP_COMMIT();

    for (int c = 0; c < NCHUNK; c++) {
        if (c < NCHUNK - 1) asm volatile("cp.async.wait_group 1;" ::: "memory");
        else                asm volatile("cp.async.wait_group 0;" ::: "memory");
        __syncthreads();

        const uint32_t st = sb + (c & 1) * STAGE_B;
        #pragma unroll
        for (int ks = 0; ks < 2; ks++) {          // two k16 steps per chunk
            const uint32_t koff = ks * 32;        // 16 bf16 = 32 bytes
            uint32_t ah[2][4], al[2][4];
            #pragma unroll
            for (int mi = 0; mi < 2; mi++) {
                ldx4(ah[mi], st + 0 * TILE_B + aoffm[mi] + koff);
                ldx4(al[mi], st + 1 * TILE_B + aoffm[mi] + koff);
            }
            #pragma unroll
            for (int p = 0; p < 4; p++) {
                uint32_t bh[4], bl[4];
                ldx4(bh, st + 2 * TILE_B + boffp[p] + koff);
                ldx4(bl, st + 3 * TILE_B + boffp[p] + koff);
                #pragma unroll
                for (int mi = 0; mi < 2; mi++) {
                    #pragma unroll
                    for (int sub = 0; sub < 2; sub++) {
                        float* d = acc[mi][p * 2 + sub];
                        const uint32_t b0 = bh[sub * 2], b1 = bh[sub * 2 + 1];
                        mma_bf16(d, ah[mi], b0, b1);                     // Ah*Bh
                        mma_bf16(d, ah[mi], bl[sub * 2], bl[sub * 2 + 1]); // Ah*Bl
                        mma_bf16(d, al[mi], b0, b1);                     // Al*Bh
                    }
                }
            }
        }
        __syncthreads();

        if (c + 2 < NCHUNK) {
            load_chunk(st, Ahb, Alb, Bhb, Blb, (c + 2) * GBK, tid);
            CP_COMMIT();
        }
    }

    // Epilogue: fp32 accum -> C (float2 stores; cols 2t,2t+1 contiguous)
    const int g = l >> 2, t2 = (l & 3) * 2;
    #pragma unroll
    for (int mi = 0; mi < 2; mi++) {
        #pragma unroll
        for (int ni = 0; ni < 8; ni++) {
            const int row = bm * 128 + wm * 32 + mi * 16 + g;
            const int col = bn * 128 + wn * 64 + ni * 8 + t2;
            float* p0 = C + (size_t)row * EMB + col;
            float* p1 = C + (size_t)(row + 8) * EMB + col;
            *(float2*)p0 = make_float2(acc[mi][ni][0], acc[mi][ni][1]);
            *(float2*)p1 = make_float2(acc[mi][ni][2], acc[mi][ni][3]);
        }
    }
}

// ---------------------------------------------------------------------------
// Causal flash attention, fp32 (unchanged; 1311us, next round's target)
// ---------------------------------------------------------------------------
#define FBR 64
#define FBC 32

__global__ void __launch_bounds__(256) flash_attn_kernel(
    const float* __restrict__ Qg, const float* __restrict__ Kg,
    const float* __restrict__ Vg, float* __restrict__ Og)
{
    __shared__ float Qs[FBR][DK + 4];
    __shared__ float Ks[FBC][DK + 1];
    __shared__ float Vs[FBC][DK + 4];
    __shared__ float Ps[FBR][FBC + 1];

    const int qb = blockIdx.x;
    const int h  = blockIdx.y;
    const int b  = blockIdx.z;
    const int tid = threadIdx.x;
    const int ty = tid >> 4;
    const int tx = tid & 15;

    const long long qrowbase = ((long long)(b * SEQ + qb * FBR)) * EMB + h * DK;
    const long long khbase   = ((long long)b * SEQ) * EMB + h * DK;

    for (int i = tid; i < FBR * (DK / 4); i += 256) {
        const int r = i >> 4;
        const int q4 = (i & 15) << 2;
        float4 v = *(const float4*)(Qg + qrowbase + (long long)r * EMB + q4);
        *(float4*)&Qs[r][q4] = v;
    }

    float m_i[4], l_i[4], acc[4][4];
    #pragma unroll
    for (int i = 0; i < 4; i++) {
        m_i[i] = -INFINITY; l_i[i] = 0.f;
        #pragma unroll
        for (int j = 0; j < 4; j++) acc[i][j] = 0.f;
    }

    __syncthreads();

    const int kbmax = 2 * qb + 1;
    for (int kb = 0; kb <= kbmax; kb++) {
        for (int i = tid; i < FBC * (DK / 4); i += 256) {
            const int r = i >> 4;
            const int q4 = (i & 15) << 2;
            const long long g = khbase + (long long)(kb * FBC + r) * EMB + q4;
            float4 k4 = *(const float4*)(Kg + g);
            Ks[r][q4 + 0] = k4.x; Ks[r][q4 + 1] = k4.y;
            Ks[r][q4 + 2] = k4.z; Ks[r][q4 + 3] = k4.w;
            float4 v4 = *(const float4*)(Vg + g);
            *(float4*)&Vs[r][q4] = v4;
        }
        __syncthreads();

        float s0[4], s1[4];
        #pragma unroll
        for (int i = 0; i < 4; i++) { s0[i] = 0.f; s1[i] = 0.f; }
        #pragma unroll 8
        for (int d = 0; d < DK; d++) {
            const float kv0 = Ks[tx * 2 + 0][d];
            const float kv1 = Ks[tx * 2 + 1][d];
            #pragma unroll
            for (int i = 0; i < 4; i++) {
                const float qv = Qs[ty * 4 + i][d];
                s0[i] += qv * kv0;
                s1[i] += qv * kv1;
            }
        }

        #pragma unroll
        for (int i = 0; i < 4; i++) {
            const int qrow = qb * FBR + ty * 4 + i;
            const int kc0 = kb * FBC + tx * 2;
            const float v0 = (kc0     <= qrow) ? s0[i] * 0.125f : -INFINITY;
            const float v1 = (kc0 + 1 <= qrow) ? s1[i] * 0.125f : -INFINITY;

            float rmax = fmaxf(v0, v1);
            #pragma unroll
            for (int w = 1; w < 16; w <<= 1)
                rmax = fmaxf(rmax, __shfl_xor_sync(0xffffffffu, rmax, w));

            const float mn = fmaxf(m_i[i], rmax);
            const float alpha = __expf(m_i[i] - mn);
            const float p0 = __expf(v0 - mn);
            const float p1 = __expf(v1 - mn);

            float rs = p0 + p1;
            #pragma unroll
            for (int w = 1; w < 16; w <<= 1)
                rs += __shfl_xor_sync(0xffffffffu, rs, w);

            l_i[i] = l_i[i] * alpha + rs;
            m_i[i] = mn;
            #pragma unroll
            for (int j = 0; j < 4; j++) acc[i][j] *= alpha;

            Ps[ty * 4 + i][tx * 2 + 0] = p0;
            Ps[ty * 4 + i][tx * 2 + 1] = p1;
        }
        __syncthreads();

        #pragma unroll 4
        for (int c = 0; c < FBC; c++) {
            const float4 v4 = *(const float4*)&Vs[c][tx * 4];
            #pragma unroll
            for (int i = 0; i < 4; i++) {
                const float p = Ps[ty * 4 + i][c];
                acc[i][0] += p * v4.x;
                acc[i][1] += p * v4.y;
                acc[i][2] += p * v4.z;
                acc[i][3] += p * v4.w;
            }
        }
        __syncthreads();
    }

    #pragma unroll
    for (int i = 0; i < 4; i++) {
        const float inv = 1.f / l_i[i];
        float4 o = make_float4(acc[i][0] * inv, acc[i][1] * inv,
                               acc[i][2] * inv, acc[i][3] * inv);
        *(float4*)(Og + qrowbase + (long long)(ty * 4 + i) * EMB + tx * 4) = o;
    }
}

// ---------------------------------------------------------------------------
// Launch
// ---------------------------------------------------------------------------
extern "C" void kernel_launch(void* const* d_in, const int* in_sizes, int n_in,
                              void* d_out, int out_size)
{
    const float* x  = (const float*)d_in[0];
    const float* W[4] = { (const float*)d_in[1], (const float*)d_in[2],
                          (const float*)d_in[3], (const float*)d_in[4] };
    float* out = (float*)d_out;

    void *pQ, *pK, *pV, *pA, *pxh, *pxl, *pah, *pal, *pwh, *pwl;
    cudaGetSymbolAddress(&pQ, g_Qp);
    cudaGetSymbolAddress(&pK, g_Kp);
    cudaGetSymbolAddress(&pV, g_Vp);
    cudaGetSymbolAddress(&pA, g_Ap);
    cudaGetSymbolAddress(&pxh, g_xh);
    cudaGetSymbolAddress(&pxl, g_xl);
    cudaGetSymbolAddress(&pah, g_ah);
    cudaGetSymbolAddress(&pal, g_al);
    cudaGetSymbolAddress(&pwh, g_wh);
    cudaGetSymbolAddress(&pwl, g_wl);

    cudaFuncSetAttribute(gemm_hmma_kernel,
                         cudaFuncAttributeMaxDynamicSharedMemorySize, GEMM_SMEM);

    __nv_bfloat16* xh = (__nv_bfloat16*)pxh;
    __nv_bfloat16* xl = (__nv_bfloat16*)pxl;
    __nv_bfloat16* ah = (__nv_bfloat16*)pah;
    __nv_bfloat16* al = (__nv_bfloat16*)pal;
    __nv_bfloat16* wh = (__nv_bfloat16*)pwh;
    __nv_bfloat16* wl = (__nv_bfloat16*)pwl;

    const int NELEM = MROWS * EMB;

    // 1) split x into bf16 hi/lo
    split_kernel<<<NELEM / 4 / 256, 256>>>(x, xh, xl, NELEM);

    // 2) transpose+split the four weight matrices
    dim3 wGrid(EMB / 32, EMB / 32), wBlk(32, 8);
    for (int i = 0; i < 4; i++)
        wsplit_kernel<<<wGrid, wBlk>>>(W[i], wh + (size_t)i * EMB * EMB,
                                       wl + (size_t)i * EMB * EMB);

    // 3) Q/K/V projections on HMMA tensor cores
    dim3 gGrid(EMB / 128, MROWS / 128);   // (8, 64)
    gemm_hmma_kernel<<<gGrid, 256, GEMM_SMEM>>>(xh, xl, wh + 0 * (size_t)EMB * EMB,
                                                wl + 0 * (size_t)EMB * EMB, (float*)pQ);
    gemm_hmma_kernel<<<gGrid, 256, GEMM_SMEM>>>(xh, xl, wh + 1 * (size_t)EMB * EMB,
                                                wl + 1 * (size_t)EMB * EMB, (float*)pK);
    gemm_hmma_kernel<<<gGrid, 256, GEMM_SMEM>>>(xh, xl, wh + 2 * (size_t)EMB * EMB,
                                                wl + 2 * (size_t)EMB * EMB, (float*)pV);

    // 4) causal flash attention (fp32)
    dim3 fGrid(SEQ / FBR, HEADS, BATCH);
    flash_attn_kernel<<<fGrid, 256>>>((const float*)pQ, (const float*)pK,
                                      (const float*)pV, (float*)pA);

    // 5) split attention output, final projection
    split_kernel<<<NELEM / 4 / 256, 256>>>((const float*)pA, ah, al, NELEM);
    gemm_hmma_kernel<<<gGrid, 256, GEMM_SMEM>>>(ah, al, wh + 3 * (size_t)EMB * EMB,
                                                wl + 3 * (size_t)EMB * EMB, out);
}

// round 10
// speedup vs baseline: 3.0714x; 1.8833x over previous
#include <cuda_runtime.h>
#include <cuda_bf16.h>
#include <math.h>
#include <stdint.h>

// Problem constants
#define BATCH 4
#define SEQ   2048
#define EMB   1024
#define HEADS 16
#define DK    64
#define MROWS (BATCH*SEQ)   // 8192
#define NELEM (MROWS*EMB)

// ---------------------------------------------------------------------------
// Scratch (static device arrays; no allocations allowed).
// g_Qp/g_Kp/g_Vp (fp32-sized) are aliased as PAIRS of bf16 arrays (hi, lo).
// ---------------------------------------------------------------------------
__device__ float g_Qp[NELEM];
__device__ float g_Kp[NELEM];
__device__ float g_Vp[NELEM];

__device__ __nv_bfloat16 g_xh[NELEM];   // x split hi
__device__ __nv_bfloat16 g_xl[NELEM];   // x split lo
__device__ __nv_bfloat16 g_ah[NELEM];   // attn out split hi
__device__ __nv_bfloat16 g_al[NELEM];   // attn out split lo
__device__ __nv_bfloat16 g_wh[4][EMB * EMB];  // W^T split hi  [n][k]
__device__ __nv_bfloat16 g_wl[4][EMB * EMB];  // W^T split lo  [n][k]

// ---------------------------------------------------------------------------
// PTX helpers (sm_80-era only; legal on plain sm_103 PTX target)
// ---------------------------------------------------------------------------
__device__ __forceinline__ uint32_t s2u(const void* p) {
    uint32_t a;
    asm("{ .reg .u64 t; cvta.to.shared.u64 t, %1; cvt.u32.u64 %0, t; }"
        : "=r"(a) : "l"(p));
    return a;
}

__device__ __forceinline__ void cpasync16(uint32_t dst, const void* src) {
    asm volatile("cp.async.cg.shared.global [%0], [%1], 16;"
                 :: "r"(dst), "l"(src));
}
#define CP_COMMIT() asm volatile("cp.async.commit_group;" ::: "memory")

__device__ __forceinline__ void ldx4(uint32_t* r, uint32_t addr) {
    asm volatile("ldmatrix.sync.aligned.m8n8.x4.shared.b16 {%0,%1,%2,%3}, [%4];"
                 : "=r"(r[0]), "=r"(r[1]), "=r"(r[2]), "=r"(r[3])
                 : "r"(addr));
}

__device__ __forceinline__ void ldx4t(uint32_t* r, uint32_t addr) {
    asm volatile("ldmatrix.sync.aligned.m8n8.x4.trans.shared.b16 {%0,%1,%2,%3}, [%4];"
                 : "=r"(r[0]), "=r"(r[1]), "=r"(r[2]), "=r"(r[3])
                 : "r"(addr));
}

__device__ __forceinline__ void mma_bf16(float* d, const uint32_t* a,
                                         uint32_t b0, uint32_t b1) {
    asm volatile("mma.sync.aligned.m16n8k16.row.col.f32.bf16.bf16.f32 "
                 "{%0,%1,%2,%3}, {%4,%5,%6,%7}, {%8,%9}, {%0,%1,%2,%3};"
                 : "+f"(d[0]), "+f"(d[1]), "+f"(d[2]), "+f"(d[3])
                 : "r"(a[0]), "r"(a[1]), "r"(a[2]), "r"(a[3]),
                   "r"(b0), "r"(b1));
}

// pack two fp32 into bf16x2 (lo = first element, little-endian low half)
__device__ __forceinline__ uint32_t packbf(float lo, float hi) {
    uint32_t r;
    asm("cvt.rn.bf16x2.f32 %0, %1, %2;" : "=r"(r) : "f"(hi), "f"(lo));
    return r;
}
// bf16x2 halves back to fp32 (exact: bf16 -> fp32 is a 16-bit shift)
__device__ __forceinline__ float bfloat_lo(uint32_t p) { return __uint_as_float(p << 16); }
__device__ __forceinline__ float bfloat_hi(uint32_t p) { return __uint_as_float(p & 0xffff0000u); }

__device__ __forceinline__ float ex2f(float x) {
    float y;
    asm("ex2.approx.ftz.f32 %0, %1;" : "=f"(y) : "f"(x));
    return y;
}

#define NEG_INF __int_as_float(0xff800000)

// ---------------------------------------------------------------------------
// Split kernel: fp32 -> (bf16 hi, bf16 lo residual)
// ---------------------------------------------------------------------------
__global__ void split_kernel(const float* __restrict__ in,
                             __nv_bfloat16* __restrict__ hi,
                             __nv_bfloat16* __restrict__ lo, int n)
{
    int i = (blockIdx.x * blockDim.x + threadIdx.x) * 4;
    if (i >= n) return;
    float4 v = *(const float4*)(in + i);
    uint32_t h01 = packbf(v.x, v.y);
    uint32_t h23 = packbf(v.z, v.w);
    uint32_t l01 = packbf(v.x - bfloat_lo(h01), v.y - bfloat_hi(h01));
    uint32_t l23 = packbf(v.z - bfloat_lo(h23), v.w - bfloat_hi(h23));
    *(uint32_t*)(hi + i)     = h01;
    *(uint32_t*)(hi + i + 2) = h23;
    *(uint32_t*)(lo + i)     = l01;
    *(uint32_t*)(lo + i + 2) = l23;
}

// ---------------------------------------------------------------------------
// Weight transpose + split: Wt[n][k] = split(W[k][n]), 32x32 smem tiles
// ---------------------------------------------------------------------------
__global__ void wsplit_kernel(const float* __restrict__ W,
                              __nv_bfloat16* __restrict__ ht,
                              __nv_bfloat16* __restrict__ lt)
{
    __shared__ float t[32][33];
    const int tx = threadIdx.x, ty = threadIdx.y;      // 32 x 8
    const int n0 = blockIdx.x * 32, k0 = blockIdx.y * 32;
    #pragma unroll
    for (int j = 0; j < 4; j++)
        t[ty + 8 * j][tx] = W[(size_t)(k0 + ty + 8 * j) * EMB + n0 + tx];
    __syncthreads();
    #pragma unroll
    for (int j = 0; j < 4; j++) {
        float v = t[tx][ty + 8 * j];
        __nv_bfloat16 h = __float2bfloat16(v);
        __nv_bfloat16 l = __float2bfloat16(v - __bfloat162float(h));
        size_t o = (size_t)(n0 + ty + 8 * j) * EMB + k0 + tx;
        ht[o] = h;
        lt[o] = l;
    }
}

// ---------------------------------------------------------------------------
// HMMA split-bf16 GEMM: C = A * W via Ah*Bh + Ah*Bl + Al*Bh.
// SPLIT_OUT=true: epilogue writes bf16 hi/lo (for Q/K/V -> flash).
// SPLIT_OUT=false: epilogue writes fp32 (final WO projection).
// ---------------------------------------------------------------------------
#define GBK       32
#define NCHUNK    (EMB / GBK)          // 32
#define TILE_B    (128 * 80)           // 10240 B per operand tile
#define STAGE_B   (4 * TILE_B)         // Ah, Al, Bh, Bl = 40960 B
#define GEMM_SMEM (2 * STAGE_B)        // 81920 B

__device__ __forceinline__ void load_chunk(uint32_t st,
    const __nv_bfloat16* Ah, const __nv_bfloat16* Al,
    const __nv_bfloat16* Bh, const __nv_bfloat16* Bl,
    int k0, int tid)
{
    const __nv_bfloat16* srcs[4] = { Ah, Al, Bh, Bl };
    #pragma unroll
    for (int t = 0; t < 4; t++) {
        const char* base = (const char*)srcs[t] + (size_t)k0 * 2;
        #pragma unroll
        for (int j = 0; j < 2; j++) {
            int idx = tid + j * 256;       // 0..511
            int row = idx >> 2;            // 0..127
            int c16 = (idx & 3) * 16;      // 0,16,32,48
            cpasync16(st + t * TILE_B + row * 80 + c16,
                      base + (size_t)row * (EMB * 2) + c16);
        }
    }
}

template<bool SPLIT_OUT>
__global__ void __launch_bounds__(256, 2) gemm_hmma_kernel(
    const __nv_bfloat16* __restrict__ Ah, const __nv_bfloat16* __restrict__ Al,
    const __nv_bfloat16* __restrict__ Bh, const __nv_bfloat16* __restrict__ Bl,
    float* __restrict__ C,
    __nv_bfloat16* __restrict__ Ch, __nv_bfloat16* __restrict__ Cl)
{
    extern __shared__ char smem[];
    const uint32_t sb = s2u(smem);
    const int tid = threadIdx.x;
    const int wid = tid >> 5, l = tid & 31;
    const int wm = wid & 3;
    const int wn = wid >> 2;
    const int bn = blockIdx.x, bm = blockIdx.y;

    const __nv_bfloat16* Ahb = Ah + (size_t)bm * 128 * EMB;
    const __nv_bfloat16* Alb = Al + (size_t)bm * 128 * EMB;
    const __nv_bfloat16* Bhb = Bh + (size_t)bn * 128 * EMB;
    const __nv_bfloat16* Blb = Bl + (size_t)bn * 128 * EMB;

    int aoffm[2];
    #pragma unroll
    for (int mi = 0; mi < 2; mi++)
        aoffm[mi] = (wm * 32 + mi * 16 + (l & 15)) * 80 + ((l >> 4) & 1) * 16;
    int boffp[4];
    #pragma unroll
    for (int p = 0; p < 4; p++)
        boffp[p] = (wn * 64 + p * 16 + (l & 7) + ((l >> 4) << 3)) * 80
                 + ((l >> 3) & 1) * 16;

    float acc[2][8][4];
    #pragma unroll
    for (int mi = 0; mi < 2; mi++)
        #pragma unroll
        for (int ni = 0; ni < 8; ni++)
            #pragma unroll
            for (int r = 0; r < 4; r++) acc[mi][ni][r] = 0.f;

    load_chunk(sb + 0 * STAGE_B, Ahb, Alb, Bhb, Blb, 0 * GBK, tid);
    CP_COMMIT();
    load_chunk(sb + 1 * STAGE_B, Ahb, Alb, Bhb, Blb, 1 * GBK, tid);
    CP_COMMIT();

    for (int c = 0; c < NCHUNK; c++) {
        if (c < NCHUNK - 1) asm volatile("cp.async.wait_group 1;" ::: "memory");
        else                asm volatile("cp.async.wait_group 0;" ::: "memory");
        __syncthreads();

        const uint32_t st = sb + (c & 1) * STAGE_B;
        #pragma unroll
        for (int ks = 0; ks < 2; ks++) {
            const uint32_t koff = ks * 32;
            uint32_t ah[2][4], al[2][4];
            #pragma unroll
            for (int mi = 0; mi < 2; mi++) {
                ldx4(ah[mi], st + 0 * TILE_B + aoffm[mi] + koff);
                ldx4(al[mi], st + 1 * TILE_B + aoffm[mi] + koff);
            }
            #pragma unroll
            for (int p = 0; p < 4; p++) {
                uint32_t bh[4], bl[4];
                ldx4(bh, st + 2 * TILE_B + boffp[p] + koff);
                ldx4(bl, st + 3 * TILE_B + boffp[p] + koff);
                #pragma unroll
                for (int mi = 0; mi < 2; mi++) {
                    #pragma unroll
                    for (int sub = 0; sub < 2; sub++) {
                        float* d = acc[mi][p * 2 + sub];
                        const uint32_t b0 = bh[sub * 2], b1 = bh[sub * 2 + 1];
                        mma_bf16(d, ah[mi], b0, b1);
                        mma_bf16(d, ah[mi], bl[sub * 2], bl[sub * 2 + 1]);
                        mma_bf16(d, al[mi], b0, b1);
                    }
                }
            }
        }
        __syncthreads();

        if (c + 2 < NCHUNK) {
            load_chunk(st, Ahb, Alb, Bhb, Blb, (c + 2) * GBK, tid);
            CP_COMMIT();
        }
    }

    const int g = l >> 2, t2 = (l & 3) * 2;
    #pragma unroll
    for (int mi = 0; mi < 2; mi++) {
        #pragma unroll
        for (int ni = 0; ni < 8; ni++) {
            const int row = bm * 128 + wm * 32 + mi * 16 + g;
            const int col = bn * 128 + wn * 64 + ni * 8 + t2;
            const size_t o0 = (size_t)row * EMB + col;
            const size_t o1 = o0 + (size_t)8 * EMB;
            if (SPLIT_OUT) {
                uint32_t h0 = packbf(acc[mi][ni][0], acc[mi][ni][1]);
                uint32_t l0 = packbf(acc[mi][ni][0] - bfloat_lo(h0),
                                     acc[mi][ni][1] - bfloat_hi(h0));
                uint32_t h1 = packbf(acc[mi][ni][2], acc[mi][ni][3]);
                uint32_t l1 = packbf(acc[mi][ni][2] - bfloat_lo(h1),
                                     acc[mi][ni][3] - bfloat_hi(h1));
                *(uint32_t*)(Ch + o0) = h0;
                *(uint32_t*)(Cl + o0) = l0;
                *(uint32_t*)(Ch + o1) = h1;
                *(uint32_t*)(Cl + o1) = l1;
            } else {
                *(float2*)(C + o0) = make_float2(acc[mi][ni][0], acc[mi][ni][1]);
                *(float2*)(C + o1) = make_float2(acc[mi][ni][2], acc[mi][ni][3]);
            }
        }
    }
}

// ---------------------------------------------------------------------------
// HMMA causal flash attention. BR=BC=64, dk=64, 4 warps (128 threads).
// Warp w owns q rows w*16..w*16+15. Split-bf16 for QK^T and P.V (lo.lo dropped).
// K/V (hi+lo) double-buffered via cp.async; Q fragments register-resident.
// SMEM rows padded to 144 B (9*16 -> conflict-free ldmatrix).
// ---------------------------------------------------------------------------
#define FSTR  144
#define FTILE (64 * FSTR)       // 9216
#define FQSZ  (2 * FTILE)       // 18432
#define FKVSZ (4 * FTILE)       // 36864 (Kh, Kl, Vh, Vl)
#define FSMEM (FQSZ + 2 * FKVSZ) // 92160

__device__ __forceinline__ void flash_loadKV(uint32_t base,
    const __nv_bfloat16* kh, const __nv_bfloat16* kl,
    const __nv_bfloat16* vh, const __nv_bfloat16* vl,
    size_t rowK, int col0, int kb, int tid)
{
    const __nv_bfloat16* srcs[4] = { kh, kl, vh, vl };
    #pragma unroll
    for (int i = 0; i < 16; i++) {
        int idx = tid + i * 128;       // 0..2047
        int tile = idx >> 9;           // 0..3
        int r = (idx >> 3) & 63;
        int c16 = (idx & 7) * 16;
        cpasync16(base + tile * FTILE + r * FSTR + c16,
                  (const char*)(srcs[tile] + (rowK + kb * 64 + r) * EMB + col0) + c16);
    }
    CP_COMMIT();
}

__global__ void __launch_bounds__(128) flash_hmma_kernel(
    const __nv_bfloat16* __restrict__ qh, const __nv_bfloat16* __restrict__ ql,
    const __nv_bfloat16* __restrict__ kh, const __nv_bfloat16* __restrict__ kl,
    const __nv_bfloat16* __restrict__ vh, const __nv_bfloat16* __restrict__ vl,
    __nv_bfloat16* __restrict__ ah, __nv_bfloat16* __restrict__ al)
{
    extern __shared__ char fsm[];
    const uint32_t sb = s2u(fsm);
    const int tid = threadIdx.x;
    const int wid = tid >> 5, l = tid & 31;
    const int qb = blockIdx.x, h = blockIdx.y, b = blockIdx.z;
    const int g = l >> 2, t = l & 3;

    const size_t rowQ = (size_t)(b * SEQ + qb * 64);
    const size_t rowK = (size_t)(b * SEQ);
    const int col0 = h * DK;

    // Stage Q hi/lo tiles (64 x 64 bf16 each)
    {
        const __nv_bfloat16* srcs[2] = { qh, ql };
        #pragma unroll
        for (int i = 0; i < 8; i++) {
            int idx = tid + i * 128;   // 0..1023
            int tile = idx >> 9;
            int r = (idx >> 3) & 63;
            int c16 = (idx & 7) * 16;
            cpasync16(sb + tile * FTILE + r * FSTR + c16,
                      (const char*)(srcs[tile] + (rowQ + r) * EMB + col0) + c16);
        }
        CP_COMMIT();
    }
    flash_loadKV(sb + FQSZ, kh, kl, vh, vl, rowK, col0, 0, tid);

    asm volatile("cp.async.wait_group 1;" ::: "memory");   // Q landed
    __syncthreads();

    // Q fragments (A of m16n8k16), register-resident for all k-steps
    uint32_t qhf[4][4], qlf[4][4];
    #pragma unroll
    for (int kt = 0; kt < 4; kt++) {
        uint32_t aoff = (uint32_t)((wid * 16 + (l & 15)) * FSTR
                                   + ((l >> 4) & 1) * 16 + kt * 32);
        ldx4(qhf[kt], sb + aoff);
        ldx4(qlf[kt], sb + FTILE + aoff);
    }

    float o[8][4];
    #pragma unroll
    for (int j = 0; j < 8; j++)
        #pragma unroll
        for (int r = 0; r < 4; r++) o[j][r] = 0.f;
    float m0 = NEG_INF, m1 = NEG_INF, sl0 = 0.f, sl1 = 0.f;
    const int lr0 = wid * 16 + g, lr1 = lr0 + 8;

    const int nkb = qb + 1;
    for (int kb = 0; kb < nkb; kb++) {
        if (kb + 1 < nkb) {
            flash_loadKV(sb + FQSZ + ((kb + 1) & 1) * FKVSZ,
                         kh, kl, vh, vl, rowK, col0, kb + 1, tid);
            asm volatile("cp.async.wait_group 1;" ::: "memory");
        } else {
            asm volatile("cp.async.wait_group 0;" ::: "memory");
        }
        __syncthreads();

        const uint32_t Kb = sb + FQSZ + (kb & 1) * FKVSZ;

        // S = Q K^T (split)
        float s[8][4];
        #pragma unroll
        for (int j = 0; j < 8; j++)
            #pragma unroll
            for (int r = 0; r < 4; r++) s[j][r] = 0.f;

        #pragma unroll
        for (int kt = 0; kt < 4; kt++) {
            #pragma unroll
            for (int p = 0; p < 4; p++) {
                uint32_t kboff = (uint32_t)((p * 16 + (l & 7) + ((l >> 4) << 3)) * FSTR
                                            + ((l >> 3) & 1) * 16 + kt * 32);
                uint32_t khb[4], klb[4];
                ldx4(khb, Kb + kboff);
                ldx4(klb, Kb + FTILE + kboff);
                #pragma unroll
                for (int sub = 0; sub < 2; sub++) {
                    float* d = s[p * 2 + sub];
                    const uint32_t b0 = khb[sub * 2], b1 = khb[sub * 2 + 1];
                    mma_bf16(d, qhf[kt], b0, b1);
                    mma_bf16(d, qhf[kt], klb[sub * 2], klb[sub * 2 + 1]);
                    mma_bf16(d, qlf[kt], b0, b1);
                }
            }
        }

        // scale (fold 1/sqrt(dk) and log2e), causal mask on diagonal block
        const float CS = 0.18033688011112042f;   // 0.125 * log2(e)
        #pragma unroll
        for (int j = 0; j < 8; j++)
            #pragma unroll
            for (int r = 0; r < 4; r++) s[j][r] *= CS;
        if (kb == qb) {
            #pragma unroll
            for (int j = 0; j < 8; j++) {
                const int c0 = j * 8 + t * 2, c1 = c0 + 1;
                if (c0 > lr0) s[j][0] = NEG_INF;
                if (c1 > lr0) s[j][1] = NEG_INF;
                if (c0 > lr1) s[j][2] = NEG_INF;
                if (c1 > lr1) s[j][3] = NEG_INF;
            }
        }

        // online softmax (fp32, fragment-register reductions)
        float rm0 = NEG_INF, rm1 = NEG_INF;
        #pragma unroll
        for (int j = 0; j < 8; j++) {
            rm0 = fmaxf(rm0, fmaxf(s[j][0], s[j][1]));
            rm1 = fmaxf(rm1, fmaxf(s[j][2], s[j][3]));
        }
        rm0 = fmaxf(rm0, __shfl_xor_sync(0xffffffffu, rm0, 1));
        rm0 = fmaxf(rm0, __shfl_xor_sync(0xffffffffu, rm0, 2));
        rm1 = fmaxf(rm1, __shfl_xor_sync(0xffffffffu, rm1, 1));
        rm1 = fmaxf(rm1, __shfl_xor_sync(0xffffffffu, rm1, 2));

        const float mn0 = fmaxf(m0, rm0), mn1 = fmaxf(m1, rm1);
        const float al0 = ex2f(m0 - mn0), al1 = ex2f(m1 - mn1);
        m0 = mn0; m1 = mn1;

        float sum0 = 0.f, sum1 = 0.f;
        #pragma unroll
        for (int j = 0; j < 8; j++) {
            s[j][0] = ex2f(s[j][0] - mn0);
            s[j][1] = ex2f(s[j][1] - mn0);
            s[j][2] = ex2f(s[j][2] - mn1);
            s[j][3] = ex2f(s[j][3] - mn1);
            sum0 += s[j][0] + s[j][1];
            sum1 += s[j][2] + s[j][3];
        }
        sum0 += __shfl_xor_sync(0xffffffffu, sum0, 1);
        sum0 += __shfl_xor_sync(0xffffffffu, sum0, 2);
        sum1 += __shfl_xor_sync(0xffffffffu, sum1, 1);
        sum1 += __shfl_xor_sync(0xffffffffu, sum1, 2);
        sl0 = sl0 * al0 + sum0;
        sl1 = sl1 * al1 + sum1;

        #pragma unroll
        for (int j = 0; j < 8; j++) {
            o[j][0] *= al0; o[j][1] *= al0;
            o[j][2] *= al1; o[j][3] *= al1;
        }

        // O += P V (P repacked from S fragments, split hi/lo; V^T via ldmatrix.trans)
        #pragma unroll
        for (int kt = 0; kt < 4; kt++) {
            uint32_t phf[4], plf[4];
            {
                const int j0 = 2 * kt, j1 = 2 * kt + 1;
                phf[0] = packbf(s[j0][0], s[j0][1]);
                phf[1] = packbf(s[j0][2], s[j0][3]);
                phf[2] = packbf(s[j1][0], s[j1][1]);
                phf[3] = packbf(s[j1][2], s[j1][3]);
                plf[0] = packbf(s[j0][0] - bfloat_lo(phf[0]), s[j0][1] - bfloat_hi(phf[0]));
                plf[1] = packbf(s[j0][2] - bfloat_lo(phf[1]), s[j0][3] - bfloat_hi(phf[1]));
                plf[2] = packbf(s[j1][0] - bfloat_lo(phf[2]), s[j1][1] - bfloat_hi(phf[2]));
                plf[3] = packbf(s[j1][2] - bfloat_lo(phf[3]), s[j1][3] - bfloat_hi(phf[3]));
            }
            #pragma unroll
            for (int p = 0; p < 4; p++) {
                uint32_t voff = (uint32_t)((kt * 16 + ((l >> 3) & 1) * 8 + (l & 7)) * FSTR
                                           + p * 32 + ((l >> 4) << 4));
                uint32_t vhb[4], vlb[4];
                ldx4t(vhb, Kb + 2 * FTILE + voff);
                ldx4t(vlb, Kb + 3 * FTILE + voff);
                #pragma unroll
                for (int sub = 0; sub < 2; sub++) {
                    float* d = o[p * 2 + sub];
                    const uint32_t b0 = vhb[sub * 2], b1 = vhb[sub * 2 + 1];
                    mma_bf16(d, phf, b0, b1);
                    mma_bf16(d, phf, vlb[sub * 2], vlb[sub * 2 + 1]);
                    mma_bf16(d, plf, b0, b1);
                }
            }
        }
        __syncthreads();
    }

    // Epilogue: normalize, split to bf16 hi/lo, store
    const float inv0 = 1.f / sl0, inv1 = 1.f / sl1;
    const size_t r0o = (rowQ + lr0) * EMB + col0;
    const size_t r1o = (rowQ + lr1) * EMB + col0;
    #pragma unroll
    for (int j = 0; j < 8; j++) {
        const int c = j * 8 + t * 2;
        float v0 = o[j][0] * inv0, v1 = o[j][1] * inv0;
        float v2 = o[j][2] * inv1, v3 = o[j][3] * inv1;
        uint32_t h0 = packbf(v0, v1);
        uint32_t l0 = packbf(v0 - bfloat_lo(h0), v1 - bfloat_hi(h0));
        uint32_t h1 = packbf(v2, v3);
        uint32_t l1 = packbf(v2 - bfloat_lo(h1), v3 - bfloat_hi(h1));
        *(uint32_t*)(ah + r0o + c) = h0;
        *(uint32_t*)(al + r0o + c) = l0;
        *(uint32_t*)(ah + r1o + c) = h1;
        *(uint32_t*)(al + r1o + c) = l1;
    }
}

// ---------------------------------------------------------------------------
// Launch
// ---------------------------------------------------------------------------
extern "C" void kernel_launch(void* const* d_in, const int* in_sizes, int n_in,
                              void* d_out, int out_size)
{
    const float* x  = (const float*)d_in[0];
    const float* W[4] = { (const float*)d_in[1], (const float*)d_in[2],
                          (const float*)d_in[3], (const float*)d_in[4] };
    float* out = (float*)d_out;

    void *pQ, *pK, *pV, *pxh, *pxl, *pah, *pal, *pwh, *pwl;
    cudaGetSymbolAddress(&pQ, g_Qp);
    cudaGetSymbolAddress(&pK, g_Kp);
    cudaGetSymbolAddress(&pV, g_Vp);
    cudaGetSymbolAddress(&pxh, g_xh);
    cudaGetSymbolAddress(&pxl, g_xl);
    cudaGetSymbolAddress(&pah, g_ah);
    cudaGetSymbolAddress(&pal, g_al);
    cudaGetSymbolAddress(&pwh, g_wh);
    cudaGetSymbolAddress(&pwl, g_wl);

    cudaFuncSetAttribute(gemm_hmma_kernel<true>,
                         cudaFuncAttributeMaxDynamicSharedMemorySize, GEMM_SMEM);
    cudaFuncSetAttribute(gemm_hmma_kernel<false>,
                         cudaFuncAttributeMaxDynamicSharedMemorySize, GEMM_SMEM);
    cudaFuncSetAttribute(flash_hmma_kernel,
                         cudaFuncAttributeMaxDynamicSharedMemorySize, FSMEM);

    __nv_bfloat16* xh = (__nv_bfloat16*)pxh;
    __nv_bfloat16* xl = (__nv_bfloat16*)pxl;
    __nv_bfloat16* ah = (__nv_bfloat16*)pah;
    __nv_bfloat16* al = (__nv_bfloat16*)pal;
    __nv_bfloat16* wh = (__nv_bfloat16*)pwh;
    __nv_bfloat16* wl = (__nv_bfloat16*)pwl;

    // fp32 scratch aliased as (hi, lo) bf16 pairs
    __nv_bfloat16* qhp = (__nv_bfloat16*)pQ; __nv_bfloat16* qlp = qhp + NELEM;
    __nv_bfloat16* khp = (__nv_bfloat16*)pK; __nv_bfloat16* klp = khp + NELEM;
    __nv_bfloat16* vhp = (__nv_bfloat16*)pV; __nv_bfloat16* vlp = vhp + NELEM;

    // 1) split x into bf16 hi/lo
    split_kernel<<<NELEM / 4 / 256, 256>>>(x, xh, xl, NELEM);

    // 2) transpose+split the four weight matrices
    dim3 wGrid(EMB / 32, EMB / 32), wBlk(32, 8);
    for (int i = 0; i < 4; i++)
        wsplit_kernel<<<wGrid, wBlk>>>(W[i], wh + (size_t)i * EMB * EMB,
                                       wl + (size_t)i * EMB * EMB);

    // 3) Q/K/V projections -> bf16 hi/lo directly
    dim3 gGrid(EMB / 128, MROWS / 128);   // (8, 64)
    gemm_hmma_kernel<true><<<gGrid, 256, GEMM_SMEM>>>(
        xh, xl, wh + 0 * (size_t)EMB * EMB, wl + 0 * (size_t)EMB * EMB,
        nullptr, qhp, qlp);
    gemm_hmma_kernel<true><<<gGrid, 256, GEMM_SMEM>>>(
        xh, xl, wh + 1 * (size_t)EMB * EMB, wl + 1 * (size_t)EMB * EMB,
        nullptr, khp, klp);
    gemm_hmma_kernel<true><<<gGrid, 256, GEMM_SMEM>>>(
        xh, xl, wh + 2 * (size_t)EMB * EMB, wl + 2 * (size_t)EMB * EMB,
        nullptr, vhp, vlp);

    // 4) causal flash attention on HMMA -> split ah/al directly
    dim3 fGrid(SEQ / 64, HEADS, BATCH);   // (32, 16, 4)
    flash_hmma_kernel<<<fGrid, 128, FSMEM>>>(qhp, qlp, khp, klp, vhp, vlp, ah, al);

    // 5) final projection (fp32 out)
    gemm_hmma_kernel<false><<<gGrid, 256, GEMM_SMEM>>>(
        ah, al, wh + 3 * (size_t)EMB * EMB, wl + 3 * (size_t)EMB * EMB,
        out, nullptr, nullptr);
}

// round 12
// speedup vs baseline: 3.3017x; 1.0750x over previous
#include <cuda_runtime.h>
#include <cuda_bf16.h>
#include <math.h>
#include <stdint.h>

// Problem constants
#define BATCH 4
#define SEQ   2048
#define EMB   1024
#define HEADS 16
#define DK    64
#define MROWS (BATCH*SEQ)   // 8192
#define NELEM (MROWS*EMB)

// ---------------------------------------------------------------------------
// Scratch (static device arrays; no allocations allowed).
// g_Qp/g_Kp/g_Vp (fp32-sized) are aliased as PAIRS of bf16 arrays (hi, lo).
// ---------------------------------------------------------------------------
__device__ float g_Qp[NELEM];
__device__ float g_Kp[NELEM];
__device__ float g_Vp[NELEM];

__device__ __nv_bfloat16 g_xh[NELEM];   // x split hi
__device__ __nv_bfloat16 g_xl[NELEM];   // x split lo
__device__ __nv_bfloat16 g_ah[NELEM];   // attn out split hi
__device__ __nv_bfloat16 g_al[NELEM];   // attn out split lo
__device__ __nv_bfloat16 g_wh[4][EMB * EMB];  // W^T split hi  [n][k]
__device__ __nv_bfloat16 g_wl[4][EMB * EMB];  // W^T split lo  [n][k]

// ---------------------------------------------------------------------------
// PTX helpers (sm_80-era only; legal on plain sm_103 PTX target)
// ---------------------------------------------------------------------------
__device__ __forceinline__ uint32_t s2u(const void* p) {
    uint32_t a;
    asm("{ .reg .u64 t; cvta.to.shared.u64 t, %1; cvt.u32.u64 %0, t; }"
        : "=r"(a) : "l"(p));
    return a;
}

__device__ __forceinline__ void cpasync16(uint32_t dst, const void* src) {
    asm volatile("cp.async.cg.shared.global [%0], [%1], 16;"
                 :: "r"(dst), "l"(src));
}
#define CP_COMMIT() asm volatile("cp.async.commit_group;" ::: "memory")

__device__ __forceinline__ void ldx4(uint32_t* r, uint32_t addr) {
    asm volatile("ldmatrix.sync.aligned.m8n8.x4.shared.b16 {%0,%1,%2,%3}, [%4];"
                 : "=r"(r[0]), "=r"(r[1]), "=r"(r[2]), "=r"(r[3])
                 : "r"(addr));
}

__device__ __forceinline__ void ldx4t(uint32_t* r, uint32_t addr) {
    asm volatile("ldmatrix.sync.aligned.m8n8.x4.trans.shared.b16 {%0,%1,%2,%3}, [%4];"
                 : "=r"(r[0]), "=r"(r[1]), "=r"(r[2]), "=r"(r[3])
                 : "r"(addr));
}

__device__ __forceinline__ void mma_bf16(float* d, const uint32_t* a,
                                         uint32_t b0, uint32_t b1) {
    asm volatile("mma.sync.aligned.m16n8k16.row.col.f32.bf16.bf16.f32 "
                 "{%0,%1,%2,%3}, {%4,%5,%6,%7}, {%8,%9}, {%0,%1,%2,%3};"
                 : "+f"(d[0]), "+f"(d[1]), "+f"(d[2]), "+f"(d[3])
                 : "r"(a[0]), "r"(a[1]), "r"(a[2]), "r"(a[3]),
                   "r"(b0), "r"(b1));
}

// pack two fp32 into bf16x2 (lo = first element, little-endian low half)
__device__ __forceinline__ uint32_t packbf(float lo, float hi) {
    uint32_t r;
    asm("cvt.rn.bf16x2.f32 %0, %1, %2;" : "=r"(r) : "f"(hi), "f"(lo));
    return r;
}
// bf16x2 halves back to fp32 (exact: bf16 -> fp32 is a 16-bit shift)
__device__ __forceinline__ float bfloat_lo(uint32_t p) { return __uint_as_float(p << 16); }
__device__ __forceinline__ float bfloat_hi(uint32_t p) { return __uint_as_float(p & 0xffff0000u); }

__device__ __forceinline__ float ex2f(float x) {
    float y;
    asm("ex2.approx.ftz.f32 %0, %1;" : "=f"(y) : "f"(x));
    return y;
}

#define NEG_INF __int_as_float(0xff800000)

// ---------------------------------------------------------------------------
// Split kernel: fp32 -> (bf16 hi, bf16 lo residual)
// ---------------------------------------------------------------------------
__global__ void split_kernel(const float* __restrict__ in,
                             __nv_bfloat16* __restrict__ hi,
                             __nv_bfloat16* __restrict__ lo, int n)
{
    int i = (blockIdx.x * blockDim.x + threadIdx.x) * 4;
    if (i >= n) return;
    float4 v = *(const float4*)(in + i);
    uint32_t h01 = packbf(v.x, v.y);
    uint32_t h23 = packbf(v.z, v.w);
    uint32_t l01 = packbf(v.x - bfloat_lo(h01), v.y - bfloat_hi(h01));
    uint32_t l23 = packbf(v.z - bfloat_lo(h23), v.w - bfloat_hi(h23));
    *(uint32_t*)(hi + i)     = h01;
    *(uint32_t*)(hi + i + 2) = h23;
    *(uint32_t*)(lo + i)     = l01;
    *(uint32_t*)(lo + i + 2) = l23;
}

// ---------------------------------------------------------------------------
// Weight transpose + split: Wt[n][k] = split(W[k][n]), 32x32 smem tiles
// ---------------------------------------------------------------------------
__global__ void wsplit_kernel(const float* __restrict__ W,
                              __nv_bfloat16* __restrict__ ht,
                              __nv_bfloat16* __restrict__ lt)
{
    __shared__ float t[32][33];
    const int tx = threadIdx.x, ty = threadIdx.y;      // 32 x 8
    const int n0 = blockIdx.x * 32, k0 = blockIdx.y * 32;
    #pragma unroll
    for (int j = 0; j < 4; j++)
        t[ty + 8 * j][tx] = W[(size_t)(k0 + ty + 8 * j) * EMB + n0 + tx];
    __syncthreads();
    #pragma unroll
    for (int j = 0; j < 4; j++) {
        float v = t[tx][ty + 8 * j];
        __nv_bfloat16 h = __float2bfloat16(v);
        __nv_bfloat16 l = __float2bfloat16(v - __bfloat162float(h));
        size_t o = (size_t)(n0 + ty + 8 * j) * EMB + k0 + tx;
        ht[o] = h;
        lt[o] = l;
    }
}

// ---------------------------------------------------------------------------
// HMMA split-bf16 GEMM core (CTA tile 128x128, BK=32, 2-stage cp.async).
// ---------------------------------------------------------------------------
#define GBK       32
#define NCHUNK    (EMB / GBK)          // 32
#define TILE_B    (128 * 80)           // 10240 B per operand tile
#define STAGE_B   (4 * TILE_B)         // Ah, Al, Bh, Bl = 40960 B
#define GEMM_SMEM (2 * STAGE_B)        // 81920 B

__device__ __forceinline__ void load_chunk(uint32_t st,
    const __nv_bfloat16* Ah, const __nv_bfloat16* Al,
    const __nv_bfloat16* Bh, const __nv_bfloat16* Bl,
    int k0, int tid)
{
    const __nv_bfloat16* srcs[4] = { Ah, Al, Bh, Bl };
    #pragma unroll
    for (int t = 0; t < 4; t++) {
        const char* base = (const char*)srcs[t] + (size_t)k0 * 2;
        #pragma unroll
        for (int j = 0; j < 2; j++) {
            int idx = tid + j * 256;       // 0..511
            int row = idx >> 2;            // 0..127
            int c16 = (idx & 3) * 16;      // 0,16,32,48
            cpasync16(st + t * TILE_B + row * 80 + c16,
                      base + (size_t)row * (EMB * 2) + c16);
        }
    }
}

// Mainloop: computes acc[2][8][4] for tile (bm, bn) of A * B.
__device__ __forceinline__ void gemm_mainloop(
    uint32_t sb, int tid,
    const __nv_bfloat16* Ahb, const __nv_bfloat16* Alb,
    const __nv_bfloat16* Bhb, const __nv_bfloat16* Blb,
    float acc[2][8][4])
{
    const int wid = tid >> 5, l = tid & 31;
    const int wm = wid & 3;
    const int wn = wid >> 2;

    int aoffm[2];
    #pragma unroll
    for (int mi = 0; mi < 2; mi++)
        aoffm[mi] = (wm * 32 + mi * 16 + (l & 15)) * 80 + ((l >> 4) & 1) * 16;
    int boffp[4];
    #pragma unroll
    for (int p = 0; p < 4; p++)
        boffp[p] = (wn * 64 + p * 16 + (l & 7) + ((l >> 4) << 3)) * 80
                 + ((l >> 3) & 1) * 16;

    #pragma unroll
    for (int mi = 0; mi < 2; mi++)
        #pragma unroll
        for (int ni = 0; ni < 8; ni++)
            #pragma unroll
            for (int r = 0; r < 4; r++) acc[mi][ni][r] = 0.f;

    load_chunk(sb + 0 * STAGE_B, Ahb, Alb, Bhb, Blb, 0 * GBK, tid);
    CP_COMMIT();
    load_chunk(sb + 1 * STAGE_B, Ahb, Alb, Bhb, Blb, 1 * GBK, tid);
    CP_COMMIT();

    for (int c = 0; c < NCHUNK; c++) {
        if (c < NCHUNK - 1) asm volatile("cp.async.wait_group 1;" ::: "memory");
        else                asm volatile("cp.async.wait_group 0;" ::: "memory");
        __syncthreads();

        const uint32_t st = sb + (c & 1) * STAGE_B;
        #pragma unroll
        for (int ks = 0; ks < 2; ks++) {
            const uint32_t koff = ks * 32;
            uint32_t ah[2][4], al[2][4];
            #pragma unroll
            for (int mi = 0; mi < 2; mi++) {
                ldx4(ah[mi], st + 0 * TILE_B + aoffm[mi] + koff);
                ldx4(al[mi], st + 1 * TILE_B + aoffm[mi] + koff);
            }
            #pragma unroll
            for (int p = 0; p < 4; p++) {
                uint32_t bh[4], bl[4];
                ldx4(bh, st + 2 * TILE_B + boffp[p] + koff);
                ldx4(bl, st + 3 * TILE_B + boffp[p] + koff);
                #pragma unroll
                for (int mi = 0; mi < 2; mi++) {
                    #pragma unroll
                    for (int sub = 0; sub < 2; sub++) {
                        float* d = acc[mi][p * 2 + sub];
                        const uint32_t b0 = bh[sub * 2], b1 = bh[sub * 2 + 1];
                        mma_bf16(d, ah[mi], b0, b1);
                        mma_bf16(d, ah[mi], bl[sub * 2], bl[sub * 2 + 1]);
                        mma_bf16(d, al[mi], b0, b1);
                    }
                }
            }
        }
        __syncthreads();

        if (c + 2 < NCHUNK) {
            load_chunk(st, Ahb, Alb, Bhb, Blb, (c + 2) * GBK, tid);
            CP_COMMIT();
        }
    }
}

// Fused Q/K/V projection: grid (24, 64); bn>>3 selects weight + output pair.
__global__ void __launch_bounds__(256, 2) gemm_qkv_kernel(
    const __nv_bfloat16* __restrict__ Ah, const __nv_bfloat16* __restrict__ Al,
    const __nv_bfloat16* __restrict__ Wh, const __nv_bfloat16* __restrict__ Wl,
    __nv_bfloat16* __restrict__ q_h, __nv_bfloat16* __restrict__ q_l,
    __nv_bfloat16* __restrict__ k_h, __nv_bfloat16* __restrict__ k_l,
    __nv_bfloat16* __restrict__ v_h, __nv_bfloat16* __restrict__ v_l)
{
    extern __shared__ char smem[];
    const uint32_t sb = s2u(smem);
    const int tid = threadIdx.x;
    const int wid = tid >> 5, l = tid & 31;
    const int bnf = blockIdx.x, bm = blockIdx.y;
    const int widx = bnf >> 3, bn = bnf & 7;

    const __nv_bfloat16* Ahb = Ah + (size_t)bm * 128 * EMB;
    const __nv_bfloat16* Alb = Al + (size_t)bm * 128 * EMB;
    const __nv_bfloat16* Bhb = Wh + (size_t)widx * EMB * EMB + (size_t)bn * 128 * EMB;
    const __nv_bfloat16* Blb = Wl + (size_t)widx * EMB * EMB + (size_t)bn * 128 * EMB;
    __nv_bfloat16* Ch = (widx == 0) ? q_h : (widx == 1) ? k_h : v_h;
    __nv_bfloat16* Cl = (widx == 0) ? q_l : (widx == 1) ? k_l : v_l;

    float acc[2][8][4];
    gemm_mainloop(sb, tid, Ahb, Alb, Bhb, Blb, acc);

    const int wm = wid & 3, wn = wid >> 2;
    const int g = l >> 2, t2 = (l & 3) * 2;
    #pragma unroll
    for (int mi = 0; mi < 2; mi++) {
        #pragma unroll
        for (int ni = 0; ni < 8; ni++) {
            const int row = bm * 128 + wm * 32 + mi * 16 + g;
            const int col = bn * 128 + wn * 64 + ni * 8 + t2;
            const size_t o0 = (size_t)row * EMB + col;
            const size_t o1 = o0 + (size_t)8 * EMB;
            uint32_t h0 = packbf(acc[mi][ni][0], acc[mi][ni][1]);
            uint32_t l0 = packbf(acc[mi][ni][0] - bfloat_lo(h0),
                                 acc[mi][ni][1] - bfloat_hi(h0));
            uint32_t h1 = packbf(acc[mi][ni][2], acc[mi][ni][3]);
            uint32_t l1 = packbf(acc[mi][ni][2] - bfloat_lo(h1),
                                 acc[mi][ni][3] - bfloat_hi(h1));
            *(uint32_t*)(Ch + o0) = h0;
            *(uint32_t*)(Cl + o0) = l0;
            *(uint32_t*)(Ch + o1) = h1;
            *(uint32_t*)(Cl + o1) = l1;
        }
    }
}

// Final WO projection: fp32 output.
__global__ void __launch_bounds__(256, 2) gemm_out_kernel(
    const __nv_bfloat16* __restrict__ Ah, const __nv_bfloat16* __restrict__ Al,
    const __nv_bfloat16* __restrict__ Bh, const __nv_bfloat16* __restrict__ Bl,
    float* __restrict__ C)
{
    extern __shared__ char smem[];
    const uint32_t sb = s2u(smem);
    const int tid = threadIdx.x;
    const int wid = tid >> 5, l = tid & 31;
    const int bn = blockIdx.x, bm = blockIdx.y;

    const __nv_bfloat16* Ahb = Ah + (size_t)bm * 128 * EMB;
    const __nv_bfloat16* Alb = Al + (size_t)bm * 128 * EMB;
    const __nv_bfloat16* Bhb = Bh + (size_t)bn * 128 * EMB;
    const __nv_bfloat16* Blb = Bl + (size_t)bn * 128 * EMB;

    float acc[2][8][4];
    gemm_mainloop(sb, tid, Ahb, Alb, Bhb, Blb, acc);

    const int wm = wid & 3, wn = wid >> 2;
    const int g = l >> 2, t2 = (l & 3) * 2;
    #pragma unroll
    for (int mi = 0; mi < 2; mi++) {
        #pragma unroll
        for (int ni = 0; ni < 8; ni++) {
            const int row = bm * 128 + wm * 32 + mi * 16 + g;
            const int col = bn * 128 + wn * 64 + ni * 8 + t2;
            const size_t o0 = (size_t)row * EMB + col;
            const size_t o1 = o0 + (size_t)8 * EMB;
            *(float2*)(C + o0) = make_float2(acc[mi][ni][0], acc[mi][ni][1]);
            *(float2*)(C + o1) = make_float2(acc[mi][ni][2], acc[mi][ni][3]);
        }
    }
}

// ---------------------------------------------------------------------------
// HMMA causal flash attention. BR=BC=64, dk=64, 4 warps (128 threads).
// Q fragments loaded DIRECTLY from global (no Q smem) -> smem 73728 B
// -> 3 CTAs/SM (12 warps) for latency hiding. K/V double-buffered cp.async.
// qb reversed so heavy (long) CTAs launch first.
// ---------------------------------------------------------------------------
#define FSTR  144
#define FTILE (64 * FSTR)        // 9216
#define FKVSZ (4 * FTILE)        // 36864 (Kh, Kl, Vh, Vl)
#define FSMEM (2 * FKVSZ)        // 73728

__device__ __forceinline__ void flash_loadKV(uint32_t base,
    const __nv_bfloat16* kh, const __nv_bfloat16* kl,
    const __nv_bfloat16* vh, const __nv_bfloat16* vl,
    size_t rowK, int col0, int kb, int tid)
{
    const __nv_bfloat16* srcs[4] = { kh, kl, vh, vl };
    #pragma unroll
    for (int i = 0; i < 16; i++) {
        int idx = tid + i * 128;       // 0..2047
        int tile = idx >> 9;           // 0..3
        int r = (idx >> 3) & 63;
        int c16 = (idx & 7) * 16;
        cpasync16(base + tile * FTILE + r * FSTR + c16,
                  (const char*)(srcs[tile] + (rowK + kb * 64 + r) * EMB + col0) + c16);
    }
    CP_COMMIT();
}

__global__ void __launch_bounds__(128, 3) flash_hmma_kernel(
    const __nv_bfloat16* __restrict__ qh, const __nv_bfloat16* __restrict__ ql,
    const __nv_bfloat16* __restrict__ kh, const __nv_bfloat16* __restrict__ kl,
    const __nv_bfloat16* __restrict__ vh, const __nv_bfloat16* __restrict__ vl,
    __nv_bfloat16* __restrict__ ah, __nv_bfloat16* __restrict__ al)
{
    extern __shared__ char fsm[];
    const uint32_t sb = s2u(fsm);
    const int tid = threadIdx.x;
    const int wid = tid >> 5, l = tid & 31;
    const int qb = (int)(gridDim.x - 1 - blockIdx.x);   // heavy CTAs first
    const int h = blockIdx.y, b = blockIdx.z;
    const int g = l >> 2, t = l & 3;

    const size_t rowQ = (size_t)(b * SEQ + qb * 64);
    const size_t rowK = (size_t)(b * SEQ);
    const int col0 = h * DK;

    // Kick off K/V stage 0 first so Q loads overlap the cp.async flight
    flash_loadKV(sb, kh, kl, vh, vl, rowK, col0, 0, tid);

    // Q fragments (A of m16n8k16) straight from global:
    // a0:(g,2t) a1:(g+8,2t) a2:(g,2t+8) a3:(g+8,2t+8) per k16 block kt
    uint32_t qhf[4][4], qlf[4][4];
    {
        const __nv_bfloat16* qrh = qh + (rowQ + wid * 16) * EMB + col0;
        const __nv_bfloat16* qrl = ql + (rowQ + wid * 16) * EMB + col0;
        #pragma unroll
        for (int kt = 0; kt < 4; kt++) {
            const int cb = kt * 16 + 2 * t;
            qhf[kt][0] = *(const uint32_t*)(qrh + (size_t)g * EMB + cb);
            qhf[kt][1] = *(const uint32_t*)(qrh + (size_t)(g + 8) * EMB + cb);
            qhf[kt][2] = *(const uint32_t*)(qrh + (size_t)g * EMB + cb + 8);
            qhf[kt][3] = *(const uint32_t*)(qrh + (size_t)(g + 8) * EMB + cb + 8);
            qlf[kt][0] = *(const uint32_t*)(qrl + (size_t)g * EMB + cb);
            qlf[kt][1] = *(const uint32_t*)(qrl + (size_t)(g + 8) * EMB + cb);
            qlf[kt][2] = *(const uint32_t*)(qrl + (size_t)g * EMB + cb + 8);
            qlf[kt][3] = *(const uint32_t*)(qrl + (size_t)(g + 8) * EMB + cb + 8);
        }
    }

    float o[8][4];
    #pragma unroll
    for (int j = 0; j < 8; j++)
        #pragma unroll
        for (int r = 0; r < 4; r++) o[j][r] = 0.f;
    float m0 = NEG_INF, m1 = NEG_INF, sl0 = 0.f, sl1 = 0.f;
    const int lr0 = wid * 16 + g, lr1 = lr0 + 8;

    const int nkb = qb + 1;
    for (int kb = 0; kb < nkb; kb++) {
        if (kb + 1 < nkb) {
            flash_loadKV(sb + ((kb + 1) & 1) * FKVSZ,
                         kh, kl, vh, vl, rowK, col0, kb + 1, tid);
            asm volatile("cp.async.wait_group 1;" ::: "memory");
        } else {
            asm volatile("cp.async.wait_group 0;" ::: "memory");
        }
        __syncthreads();

        const uint32_t Kb = sb + (kb & 1) * FKVSZ;

        // S = Q K^T (split)
        float s[8][4];
        #pragma unroll
        for (int j = 0; j < 8; j++)
            #pragma unroll
            for (int r = 0; r < 4; r++) s[j][r] = 0.f;

        #pragma unroll
        for (int kt = 0; kt < 4; kt++) {
            #pragma unroll
            for (int p = 0; p < 4; p++) {
                uint32_t kboff = (uint32_t)((p * 16 + (l & 7) + ((l >> 4) << 3)) * FSTR
                                            + ((l >> 3) & 1) * 16 + kt * 32);
                uint32_t khb[4], klb[4];
                ldx4(khb, Kb + kboff);
                ldx4(klb, Kb + FTILE + kboff);
                #pragma unroll
                for (int sub = 0; sub < 2; sub++) {
                    float* d = s[p * 2 + sub];
                    const uint32_t b0 = khb[sub * 2], b1 = khb[sub * 2 + 1];
                    mma_bf16(d, qhf[kt], b0, b1);
                    mma_bf16(d, qhf[kt], klb[sub * 2], klb[sub * 2 + 1]);
                    mma_bf16(d, qlf[kt], b0, b1);
                }
            }
        }

        // scale (fold 1/sqrt(dk) and log2e), causal mask on diagonal block
        const float CS = 0.18033688011112042f;   // 0.125 * log2(e)
        #pragma unroll
        for (int j = 0; j < 8; j++)
            #pragma unroll
            for (int r = 0; r < 4; r++) s[j][r] *= CS;
        if (kb == qb) {
            #pragma unroll
            for (int j = 0; j < 8; j++) {
                const int c0 = j * 8 + t * 2, c1 = c0 + 1;
                if (c0 > lr0) s[j][0] = NEG_INF;
                if (c1 > lr0) s[j][1] = NEG_INF;
                if (c0 > lr1) s[j][2] = NEG_INF;
                if (c1 > lr1) s[j][3] = NEG_INF;
            }
        }

        // online softmax (fp32, fragment-register reductions)
        float rm0 = NEG_INF, rm1 = NEG_INF;
        #pragma unroll
        for (int j = 0; j < 8; j++) {
            rm0 = fmaxf(rm0, fmaxf(s[j][0], s[j][1]));
            rm1 = fmaxf(rm1, fmaxf(s[j][2], s[j][3]));
        }
        rm0 = fmaxf(rm0, __shfl_xor_sync(0xffffffffu, rm0, 1));
        rm0 = fmaxf(rm0, __shfl_xor_sync(0xffffffffu, rm0, 2));
        rm1 = fmaxf(rm1, __shfl_xor_sync(0xffffffffu, rm1, 1));
        rm1 = fmaxf(rm1, __shfl_xor_sync(0xffffffffu, rm1, 2));

        const float mn0 = fmaxf(m0, rm0), mn1 = fmaxf(m1, rm1);
        const float al0 = ex2f(m0 - mn0), al1 = ex2f(m1 - mn1);
        m0 = mn0; m1 = mn1;

        float sum0 = 0.f, sum1 = 0.f;
        #pragma unroll
        for (int j = 0; j < 8; j++) {
            s[j][0] = ex2f(s[j][0] - mn0);
            s[j][1] = ex2f(s[j][1] - mn0);
            s[j][2] = ex2f(s[j][2] - mn1);
            s[j][3] = ex2f(s[j][3] - mn1);
            sum0 += s[j][0] + s[j][1];
            sum1 += s[j][2] + s[j][3];
        }
        sum0 += __shfl_xor_sync(0xffffffffu, sum0, 1);
        sum0 += __shfl_xor_sync(0xffffffffu, sum0, 2);
        sum1 += __shfl_xor_sync(0xffffffffu, sum1, 1);
        sum1 += __shfl_xor_sync(0xffffffffu, sum1, 2);
        sl0 = sl0 * al0 + sum0;
        sl1 = sl1 * al1 + sum1;

        #pragma unroll
        for (int j = 0; j < 8; j++) {
            o[j][0] *= al0; o[j][1] *= al0;
            o[j][2] *= al1; o[j][3] *= al1;
        }

        // O += P V (P repacked from S fragments, split hi/lo; V^T via ldmatrix.trans)
        #pragma unroll
        for (int kt = 0; kt < 4; kt++) {
            uint32_t phf[4], plf[4];
            {
                const int j0 = 2 * kt, j1 = 2 * kt + 1;
                phf[0] = packbf(s[j0][0], s[j0][1]);
                phf[1] = packbf(s[j0][2], s[j0][3]);
                phf[2] = packbf(s[j1][0], s[j1][1]);
                phf[3] = packbf(s[j1][2], s[j1][3]);
                plf[0] = packbf(s[j0][0] - bfloat_lo(phf[0]), s[j0][1] - bfloat_hi(phf[0]));
                plf[1] = packbf(s[j0][2] - bfloat_lo(phf[1]), s[j0][3] - bfloat_hi(phf[1]));
                plf[2] = packbf(s[j1][0] - bfloat_lo(phf[2]), s[j1][1] - bfloat_hi(phf[2]));
                plf[3] = packbf(s[j1][2] - bfloat_lo(phf[3]), s[j1][3] - bfloat_hi(phf[3]));
            }
            #pragma unroll
            for (int p = 0; p < 4; p++) {
                uint32_t voff = (uint32_t)((kt * 16 + ((l >> 3) & 1) * 8 + (l & 7)) * FSTR
                                           + p * 32 + ((l >> 4) << 4));
                uint32_t vhb[4], vlb[4];
                ldx4t(vhb, Kb + 2 * FTILE + voff);
                ldx4t(vlb, Kb + 3 * FTILE + voff);
                #pragma unroll
                for (int sub = 0; sub < 2; sub++) {
                    float* d = o[p * 2 + sub];
                    const uint32_t b0 = vhb[sub * 2], b1 = vhb[sub * 2 + 1];
                    mma_bf16(d, phf, b0, b1);
                    mma_bf16(d, phf, vlb[sub * 2], vlb[sub * 2 + 1]);
                    mma_bf16(d, plf, b0, b1);
                }
            }
        }
        __syncthreads();
    }

    // Epilogue: normalize, split to bf16 hi/lo, store
    const float inv0 = 1.f / sl0, inv1 = 1.f / sl1;
    const size_t r0o = (rowQ + lr0) * EMB + col0;
    const size_t r1o = (rowQ + lr1) * EMB + col0;
    #pragma unroll
    for (int j = 0; j < 8; j++) {
        const int c = j * 8 + t * 2;
        float v0 = o[j][0] * inv0, v1 = o[j][1] * inv0;
        float v2 = o[j][2] * inv1, v3 = o[j][3] * inv1;
        uint32_t h0 = packbf(v0, v1);
        uint32_t l0 = packbf(v0 - bfloat_lo(h0), v1 - bfloat_hi(h0));
        uint32_t h1 = packbf(v2, v3);
        uint32_t l1 = packbf(v2 - bfloat_lo(h1), v3 - bfloat_hi(h1));
        *(uint32_t*)(ah + r0o + c) = h0;
        *(uint32_t*)(al + r0o + c) = l0;
        *(uint32_t*)(ah + r1o + c) = h1;
        *(uint32_t*)(al + r1o + c) = l1;
    }
}

// ---------------------------------------------------------------------------
// Launch
// ---------------------------------------------------------------------------
extern "C" void kernel_launch(void* const* d_in, const int* in_sizes, int n_in,
                              void* d_out, int out_size)
{
    const float* x  = (const float*)d_in[0];
    const float* W[4] = { (const float*)d_in[1], (const float*)d_in[2],
                          (const float*)d_in[3], (const float*)d_in[4] };
    float* out = (float*)d_out;

    void *pQ, *pK, *pV, *pxh, *pxl, *pah, *pal, *pwh, *pwl;
    cudaGetSymbolAddress(&pQ, g_Qp);
    cudaGetSymbolAddress(&pK, g_Kp);
    cudaGetSymbolAddress(&pV, g_Vp);
    cudaGetSymbolAddress(&pxh, g_xh);
    cudaGetSymbolAddress(&pxl, g_xl);
    cudaGetSymbolAddress(&pah, g_ah);
    cudaGetSymbolAddress(&pal, g_al);
    cudaGetSymbolAddress(&pwh, g_wh);
    cudaGetSymbolAddress(&pwl, g_wl);

    cudaFuncSetAttribute(gemm_qkv_kernel,
                         cudaFuncAttributeMaxDynamicSharedMemorySize, GEMM_SMEM);
    cudaFuncSetAttribute(gemm_out_kernel,
                         cudaFuncAttributeMaxDynamicSharedMemorySize, GEMM_SMEM);
    cudaFuncSetAttribute(flash_hmma_kernel,
                         cudaFuncAttributeMaxDynamicSharedMemorySize, FSMEM);

    __nv_bfloat16* xh = (__nv_bfloat16*)pxh;
    __nv_bfloat16* xl = (__nv_bfloat16*)pxl;
    __nv_bfloat16* ah = (__nv_bfloat16*)pah;
    __nv_bfloat16* al = (__nv_bfloat16*)pal;
    __nv_bfloat16* wh = (__nv_bfloat16*)pwh;
    __nv_bfloat16* wl = (__nv_bfloat16*)pwl;

    // fp32 scratch aliased as (hi, lo) bf16 pairs
    __nv_bfloat16* qhp = (__nv_bfloat16*)pQ; __nv_bfloat16* qlp = qhp + NELEM;
    __nv_bfloat16* khp = (__nv_bfloat16*)pK; __nv_bfloat16* klp = khp + NELEM;
    __nv_bfloat16* vhp = (__nv_bfloat16*)pV; __nv_bfloat16* vlp = vhp + NELEM;

    // 1) split x into bf16 hi/lo
    split_kernel<<<NELEM / 4 / 256, 256>>>(x, xh, xl, NELEM);

    // 2) transpose+split the four weight matrices
    dim3 wGrid(EMB / 32, EMB / 32), wBlk(32, 8);
    for (int i = 0; i < 4; i++)
        wsplit_kernel<<<wGrid, wBlk>>>(W[i], wh + (size_t)i * EMB * EMB,
                                       wl + (size_t)i * EMB * EMB);

    // 3) fused Q/K/V projections -> bf16 hi/lo directly
    dim3 gGrid(3 * EMB / 128, MROWS / 128);   // (24, 64)
    gemm_qkv_kernel<<<gGrid, 256, GEMM_SMEM>>>(
        xh, xl, wh, wl, qhp, qlp, khp, klp, vhp, vlp);

    // 4) causal flash attention on HMMA -> split ah/al directly
    dim3 fGrid(SEQ / 64, HEADS, BATCH);   // (32, 16, 4)
    flash_hmma_kernel<<<fGrid, 128, FSMEM>>>(qhp, qlp, khp, klp, vhp, vlp, ah, al);

    // 5) final projection (fp32 out)
    dim3 oGrid(EMB / 128, MROWS / 128);   // (8, 64)
    gemm_out_kernel<<<oGrid, 256, GEMM_SMEM>>>(
        ah, al, wh + 3 * (size_t)EMB * EMB, wl + 3 * (size_t)EMB * EMB, out);
}